// round 8
// baseline (speedup 1.0000x reference)
#include <cuda_runtime.h>
#include <math.h>

#define NPAD 129
#define NT   512
#define PI_F 3.14159265358979f

// ---------------- device scratch (static: no allocation allowed) -------------
__device__ float2 g_ihat [64  * 16384];    // FFT2(image), digit-rev layout
__device__ float2 g_u1hat[1024 * 16384];   // FFT2(|u1|),  digit-rev layout
__device__ float  g_psi  [16  * 16384];    // Morlet bank, digit-rev layout
__device__ float  g_s0   [64];
__device__ float  g_s1part[1024];
__device__ float  g_s2part[6144];

// digit-reversal for radix [8,4,4] DIF: freq f -> storage position
__device__ __forceinline__ int dperm(int f) {
    return ((f & 7) << 4) | (((f >> 3) & 3) << 2) | (f >> 5);
}

// ---------------- filter bank, stored pre-permuted ---------------------------
__global__ void init_psi_kernel() {
    int idx = blockIdx.x * blockDim.x + threadIdx.x;
    if (idx >= 16 * 16384) return;
    int fc = idx & 127;
    int fr = (idx >> 7) & 127;
    int l  = (idx >> 14) & 3;
    int j  = idx >> 16;
    const float w = 2.f * PI_F / 128.f;
    float fx = (float)((fr < 64) ? fr : fr - 128) * w;
    float fy = (float)((fc < 64) ? fc : fc - 128) * w;
    float k0 = (3.f * PI_F / 4.f) / (float)(1 << j);
    float sg = 0.8f * (float)(1 << j);
    float th = PI_F * (float)l / 4.f;
    float k0x = k0 * cosf(th), k0y = k0 * sinf(th);
    float hs = 0.5f * sg * sg;
    float beta = expf(-hs * k0 * k0);
    float gs = expf(-hs * ((fx - k0x) * (fx - k0x) + (fy - k0y) * (fy - k0y)));
    float g0 = expf(-hs * (fx * fx + fy * fy));
    g_psi[((j * 4 + l) << 14) + (dperm(fr) << 7) + dperm(fc)] = gs - beta * g0;
}

__device__ __forceinline__ float2 cmul(float2 a, float2 b) {
    return make_float2(a.x * b.x - a.y * b.y, a.x * b.y + a.y * b.x);
}

// ---------------- register butterflies (interleaved complex) -----------------
template <bool INV>
__device__ __forceinline__ void bfly4(float2* x) {
    float t0r = x[0].x + x[2].x, t0i = x[0].y + x[2].y;
    float t1r = x[0].x - x[2].x, t1i = x[0].y - x[2].y;
    float t2r = x[1].x + x[3].x, t2i = x[1].y + x[3].y;
    float t3r = x[1].x - x[3].x, t3i = x[1].y - x[3].y;
    x[0].x = t0r + t2r; x[0].y = t0i + t2i;
    x[2].x = t0r - t2r; x[2].y = t0i - t2i;
    if (!INV) {
        x[1].x = t1r + t3i; x[1].y = t1i - t3r;
        x[3].x = t1r - t3i; x[3].y = t1i + t3r;
    } else {
        x[1].x = t1r - t3i; x[1].y = t1i + t3r;
        x[3].x = t1r + t3i; x[3].y = t1i - t3r;
    }
}

template <bool INV>
__device__ __forceinline__ void bfly8(float2* x) {
    const float C = 0.70710678118654752f;
    float t0r = x[0].x + x[4].x, t0i = x[0].y + x[4].y;
    float t1r = x[0].x - x[4].x, t1i = x[0].y - x[4].y;
    float t2r = x[2].x + x[6].x, t2i = x[2].y + x[6].y;
    float t3r = x[2].x - x[6].x, t3i = x[2].y - x[6].y;
    float e0r = t0r + t2r, e0i = t0i + t2i;
    float e2r = t0r - t2r, e2i = t0i - t2i;
    float e1r, e1i, e3r, e3i;
    if (!INV) { e1r = t1r + t3i; e1i = t1i - t3r; e3r = t1r - t3i; e3i = t1i + t3r; }
    else      { e1r = t1r - t3i; e1i = t1i + t3r; e3r = t1r + t3i; e3i = t1i - t3r; }
    float u0r = x[1].x + x[5].x, u0i = x[1].y + x[5].y;
    float u1r = x[1].x - x[5].x, u1i = x[1].y - x[5].y;
    float u2r = x[3].x + x[7].x, u2i = x[3].y + x[7].y;
    float u3r = x[3].x - x[7].x, u3i = x[3].y - x[7].y;
    float o0r = u0r + u2r, o0i = u0i + u2i;
    float o2r = u0r - u2r, o2i = u0i - u2i;
    float o1r, o1i, o3r, o3i;
    if (!INV) { o1r = u1r + u3i; o1i = u1i - u3r; o3r = u1r - u3i; o3i = u1i + u3r; }
    else      { o1r = u1r - u3i; o1i = u1i + u3r; o3r = u1r + u3i; o3i = u1i - u3r; }
    float w1r, w1i, w2r, w2i, w3r, w3i;
    if (!INV) {
        w1r = C * (o1r + o1i); w1i = C * (o1i - o1r);
        w2r = o2i;             w2i = -o2r;
        w3r = C * (o3i - o3r); w3i = -C * (o3r + o3i);
    } else {
        w1r = C * (o1r - o1i); w1i = C * (o1i + o1r);
        w2r = -o2i;            w2i = o2r;
        w3r = -C * (o3r + o3i); w3i = C * (o3r - o3i);
    }
    x[0].x = e0r + o0r; x[0].y = e0i + o0i;
    x[1].x = e1r + w1r; x[1].y = e1i + w1i;
    x[2].x = e2r + w2r; x[2].y = e2i + w2i;
    x[3].x = e3r + w3r; x[3].y = e3i + w3i;
    x[4].x = e0r - o0r; x[4].y = e0i - o0i;
    x[5].x = e1r - w1r; x[5].y = e1i - w1i;
    x[6].x = e2r - w2r; x[6].y = e2i - w2i;
    x[7].x = e3r - w3r; x[7].y = e3i - w3i;
}

// ---- combined [r4-mid (stride4) + r4-last (stride1)] on 16 register points --
template <bool INV>
__device__ __forceinline__ void comb_regs(float2* x, const float* twr, const float* twi) {
    if (!INV) {
#pragma unroll
        for (int j = 0; j < 4; j++) {
            float2 y[4];
#pragma unroll
            for (int k = 0; k < 4; k++) y[k] = x[j + 4 * k];
            bfly4<false>(y);
#pragma unroll
            for (int k = 1; k < 4; k++) {
                int ti = 8 * j * k;
                float wr = twr[ti], wi = twi[ti];
                float a = y[k].x, b = y[k].y;
                y[k].x = a * wr - b * wi; y[k].y = a * wi + b * wr;
            }
#pragma unroll
            for (int k = 0; k < 4; k++) x[j + 4 * k] = y[k];
        }
#pragma unroll
        for (int a = 0; a < 4; a++) bfly4<false>(&x[4 * a]);
    } else {
#pragma unroll
        for (int a = 0; a < 4; a++) bfly4<true>(&x[4 * a]);
#pragma unroll
        for (int j = 0; j < 4; j++) {
            float2 y[4];
#pragma unroll
            for (int k = 0; k < 4; k++) y[k] = x[j + 4 * k];
#pragma unroll
            for (int k = 1; k < 4; k++) {
                int ti = 8 * j * k;
                float wr = twr[ti], wi = -twi[ti];
                float a = y[k].x, b = y[k].y;
                y[k].x = a * wr - b * wi; y[k].y = a * wi + b * wr;
            }
            bfly4<true>(y);
#pragma unroll
            for (int k = 0; k < 4; k++) x[j + 4 * k] = y[k];
        }
    }
}

// ---- inverse lane-DFT8 (omega = e^{+2pi i/8}) across 8-lane subgroups -------
// input: lane k holds element K=k (already pre-twiddled).
// output: lane k holds Y[bitrev3(k)].
__device__ __forceinline__ float2 lane_dft8_inv(float2 v, int k) {
    const float C = 0.70710678118654752f;
    float2 p;
    // stage distance 4
    p.x = __shfl_xor_sync(0xffffffffu, v.x, 4);
    p.y = __shfl_xor_sync(0xffffffffu, v.y, 4);
    if ((k & 4) == 0) { v.x += p.x; v.y += p.y; }
    else {
        float dr = p.x - v.x, di = p.y - v.y;
        int t = k & 3;   // omega8^t = (cos(pi t/4), sin(pi t/4))
        float wr = (t == 0) ? 1.f : (t == 1) ? C : (t == 2) ? 0.f : -C;
        float wi = (t == 0) ? 0.f : (t == 1) ? C : (t == 2) ? 1.f : C;
        v.x = dr * wr - di * wi; v.y = dr * wi + di * wr;
    }
    // stage distance 2
    p.x = __shfl_xor_sync(0xffffffffu, v.x, 2);
    p.y = __shfl_xor_sync(0xffffffffu, v.y, 2);
    if ((k & 2) == 0) { v.x += p.x; v.y += p.y; }
    else {
        float dr = p.x - v.x, di = p.y - v.y;
        if (k & 1) { v.x = -di; v.y = dr; }      // * i (inverse)
        else       { v.x = dr;  v.y = di; }
    }
    // stage distance 1
    p.x = __shfl_xor_sync(0xffffffffu, v.x, 1);
    p.y = __shfl_xor_sync(0xffffffffu, v.y, 1);
    if ((k & 1) == 0) { v.x += p.x; v.y += p.y; }
    else { v.x = p.x - v.x; v.y = p.y - v.y; }
    return v;
}

// swizzled smem address (float2 units): conflict-free for both row stores
// (8 lanes holding c-blocks 16*nb) and strided column loads (r = 16k+j).
__device__ __forceinline__ int smaddr(int r, int c) {
    int nb = c >> 4, jc = c & 15;
    return r * 129 + ((r >> 4) << 1) + (nb << 4) + ((jc + 2 * nb) & 15);
}

// ---------------- legacy smem passes (used by kA / kB) -----------------------
template <bool INV, int DIM>
__device__ __forceinline__ void comb_stage(float2* sc, const float* twr, const float* twi) {
    for (int idx = threadIdx.x; idx < 1024; idx += NT) {
        int q = idx & 127, g = idx >> 7;
        int base = (DIM == 0) ? q * NPAD + (g << 4) : (g << 4) * NPAD + q;
        int step = (DIM == 0) ? 1 : NPAD;
        float2 x[16];
#pragma unroll
        for (int m = 0; m < 16; m++) x[m] = sc[base + m * step];
        comb_regs<INV>(x, twr, twi);
#pragma unroll
        for (int m = 0; m < 16; m++) sc[base + m * step] = x[m];
    }
    __syncthreads();
}

template <bool INV, int DIM>
__device__ __forceinline__ void r8_stage(float2* sc, const float* twr, const float* twi) {
    for (int idx = threadIdx.x; idx < 2048; idx += NT) {
        int q = idx & 127, j = idx >> 7;
        int base = (DIM == 0) ? q * NPAD + j : j * NPAD + q;
        int step = (DIM == 0) ? 16 : 16 * NPAD;
        float2 x[8];
#pragma unroll
        for (int k = 0; k < 8; k++) x[k] = sc[base + k * step];
        if (INV) {
#pragma unroll
            for (int k = 1; k < 8; k++) {
                int t = j * k;
                float wr = twr[t], wi = -twi[t];
                float a = x[k].x, b = x[k].y;
                x[k].x = a * wr - b * wi; x[k].y = a * wi + b * wr;
            }
        }
        bfly8<INV>(x);
        if (!INV) {
#pragma unroll
            for (int k = 1; k < 8; k++) {
                int t = j * k;
                float wr = twr[t], wi = twi[t];
                float a = x[k].x, b = x[k].y;
                x[k].x = a * wr - b * wi; x[k].y = a * wi + b * wr;
            }
        }
#pragma unroll
        for (int k = 0; k < 8; k++) sc[base + k * step] = x[k];
    }
    __syncthreads();
}

__device__ __forceinline__ void pass_load_inv0(float2* sc, const float2* __restrict__ src,
                                               const float* __restrict__ psi,
                                               const float* twr, const float* twi) {
    const float scale = 1.f / 16384.f;
    for (int idx = threadIdx.x; idx < 1024; idx += NT) {
        int rr = idx & 127, g = idx >> 7;
        int gbase = rr * 128 + (g << 4);
        const float4* s4 = reinterpret_cast<const float4*>(src + gbase);
        const float4* p4 = reinterpret_cast<const float4*>(psi + gbase);
        float2 x[16];
#pragma unroll
        for (int m8 = 0; m8 < 4; m8++) {
            float4 p = p4[m8];
            float4 v0 = s4[m8 * 2], v1 = s4[m8 * 2 + 1];
            float pa = p.x * scale, pb = p.y * scale, pc = p.z * scale, pd = p.w * scale;
            x[m8 * 4 + 0] = make_float2(v0.x * pa, v0.y * pa);
            x[m8 * 4 + 1] = make_float2(v0.z * pb, v0.w * pb);
            x[m8 * 4 + 2] = make_float2(v1.x * pc, v1.y * pc);
            x[m8 * 4 + 3] = make_float2(v1.z * pd, v1.w * pd);
        }
        comb_regs<true>(x, twr, twi);
        int base = rr * NPAD + (g << 4);
#pragma unroll
        for (int m = 0; m < 16; m++) sc[base + m] = x[m];
    }
    __syncthreads();
}

template <bool WRITE>
__device__ __forceinline__ float pass_inv1_r8_mag(float2* sc, const float* twr, const float* twi) {
    float local = 0.f;
    for (int idx = threadIdx.x; idx < 2048; idx += NT) {
        int q = idx & 127, j = idx >> 7;
        int base = j * NPAD + q;
        int step = 16 * NPAD;
        float2 x[8];
#pragma unroll
        for (int k = 0; k < 8; k++) x[k] = sc[base + k * step];
#pragma unroll
        for (int k = 1; k < 8; k++) {
            int t = j * k;
            float wr = twr[t], wi = -twi[t];
            float a = x[k].x, b = x[k].y;
            x[k].x = a * wr - b * wi; x[k].y = a * wi + b * wr;
        }
        bfly8<true>(x);
#pragma unroll
        for (int k = 0; k < 8; k++) {
            float mag = sqrtf(x[k].x * x[k].x + x[k].y * x[k].y);
            local += mag;
            if (WRITE) sc[base + k * step] = make_float2(mag, 0.f);
        }
    }
    __syncthreads();
    return local;
}

__device__ __forceinline__ void pass_fwd1_store(float2* sc, float2* __restrict__ dst,
                                                const float* twr, const float* twi) {
    for (int idx = threadIdx.x; idx < 1024; idx += NT) {
        int q = idx & 127, g = idx >> 7;
        int base = (g << 4) * NPAD + q;
        float2 x[16];
#pragma unroll
        for (int m = 0; m < 16; m++) x[m] = sc[base + m * NPAD];
        comb_regs<false>(x, twr, twi);
#pragma unroll
        for (int m = 0; m < 16; m++) dst[((g << 4) + m) * 128 + q] = x[m];
    }
}

#define INIT_TWIDDLES()                                                        \
    do {                                                                       \
        if (threadIdx.x < 128) {                                               \
            float sv, cv;                                                      \
            __sincosf(-2.f * PI_F * (float)threadIdx.x / 128.f, &sv, &cv);     \
            s_twr[threadIdx.x] = cv;                                           \
            s_twi[threadIdx.x] = sv;                                           \
        }                                                                      \
    } while (0)

// warp-shuffle block reduction (deterministic); result valid in tid 0
__device__ __forceinline__ float block_sum(float v, float* red) {
#pragma unroll
    for (int o = 16; o; o >>= 1) v += __shfl_xor_sync(0xffffffffu, v, o);
    if ((threadIdx.x & 31) == 0) red[threadIdx.x >> 5] = v;
    __syncthreads();
    float s = 0.f;
    if (threadIdx.x < 32) {
        s = (threadIdx.x < NT / 32) ? red[threadIdx.x] : 0.f;
#pragma unroll
        for (int o = 16; o; o >>= 1) s += __shfl_xor_sync(0xffffffffu, s, o);
    }
    return s;
}

// ---------------- stage A: i_hat = FFT2(image), s0 ---------------------------
__global__ __launch_bounds__(NT, 1) void kA(const float* __restrict__ img) {
    extern __shared__ float2 sc[];
    __shared__ float s_twr[128], s_twi[128];
    __shared__ float red[NT / 32];
    int b = blockIdx.x;
    int tid = threadIdx.x;
    INIT_TWIDDLES();

    float local = 0.f;
    for (int idx = tid; idx < 16384; idx += NT) {
        float v = img[b * 16384 + idx];
        int r = idx >> 7, c = idx & 127;
        sc[r * NPAD + c] = make_float2(v, 0.f);
        local += v;
    }
    float s = block_sum(local, red);
    if (tid == 0) g_s0[b] = s * (1.f / 16384.f);
    __syncthreads();

    r8_stage<false, 0>(sc, s_twr, s_twi);
    comb_stage<false, 0>(sc, s_twr, s_twi);
    r8_stage<false, 1>(sc, s_twr, s_twi);
    comb_stage<false, 1>(sc, s_twr, s_twi);

    for (int idx = tid; idx < 16384; idx += NT) {
        int r = idx >> 7, c = idx & 127;
        g_ihat[b * 16384 + idx] = sc[r * NPAD + c];
    }
}

// ---------------- stage B: u1 = |ifft2(i_hat*psi)|, s1 partial, u1_hat -------
__global__ __launch_bounds__(NT, 1) void kB() {
    extern __shared__ float2 sc[];
    __shared__ float s_twr[128], s_twi[128];
    __shared__ float red[NT / 32];
    int bi = blockIdx.x;              // b*16 + j1*4 + l1
    int b  = bi >> 4;
    int j1 = (bi >> 2) & 3;
    int tid = threadIdx.x;
    INIT_TWIDDLES();
    __syncthreads();

    const float2* src = g_ihat + (size_t)b * 16384;
    const float*  psi1 = g_psi + (((size_t)(bi & 15)) << 14);

    pass_load_inv0(sc, src, psi1, s_twr, s_twi);
    r8_stage<true, 0>(sc, s_twr, s_twi);
    comb_stage<true, 1>(sc, s_twr, s_twi);
    float local = pass_inv1_r8_mag<true>(sc, s_twr, s_twi);
    float s = block_sum(local, red);
    if (tid == 0) g_s1part[bi] = s;
    __syncthreads();

    if (j1 < 3) {                     // j1 == 3 never consumed by second order
        r8_stage<false, 0>(sc, s_twr, s_twi);
        comb_stage<false, 0>(sc, s_twr, s_twi);
        r8_stage<false, 1>(sc, s_twr, s_twi);
        pass_fwd1_store(sc, g_u1hat + (size_t)bi * 16384, s_twr, s_twi);
    }
}

// ---------------- stage C: lane-cooperative register-resident version --------
// inverse 2D FFT with 1 smem write + 1 smem read per tile.
__global__ __launch_bounds__(NT, 1) void kC() {
    extern __shared__ float2 sc[];
    __shared__ float s_twr[128], s_twi[128];
    __shared__ float red[NT / 32];
    int bi = blockIdx.x;              // b*96 + pair*16 + l1*4 + l2
    int b    = bi / 96;
    int r96  = bi % 96;
    int pair = r96 >> 4;
    int l1   = (r96 >> 2) & 3;
    int l2   = r96 & 3;
    const int J1[6] = {0, 0, 0, 1, 1, 2};
    const int J2[6] = {1, 2, 3, 2, 3, 3};
    int j1 = J1[pair], j2 = J2[pair];
    int tid = threadIdx.x;
    int k   = tid & 7;                // lane within 8-lane group
    int grp = tid >> 3;               // 0..63
    int n   = ((k & 1) << 2) | (k & 2) | ((k >> 2) & 1);   // bitrev3(k)
    INIT_TWIDDLES();

    // per-lane pre-twiddle ratio: conj(W128^k) = e^{+2pi i k/128}
    float c128s, c128c;
    __sincosf(2.f * PI_F * (float)k / 128.f, &c128s, &c128c);
    const float2 c128 = make_float2(c128c, c128s);
    __syncthreads();

    const float2* src = g_u1hat + (((size_t)b * 16 + j1 * 4 + l1) << 14);
    const float*  psi = g_psi + (((size_t)j2 * 4 + l2) << 14);
    const float scale = 1.f / 16384.f;

    // ---- dim0 (along c): full line inverse in registers, store swizzled -----
#pragma unroll
    for (int it = 0; it < 2; it++) {
        int r = grp + (it << 6);
        const float4* s4 = reinterpret_cast<const float4*>(src + r * 128 + 16 * k);
        const float4* p4 = reinterpret_cast<const float4*>(psi + r * 128 + 16 * k);
        float2 x[16];
#pragma unroll
        for (int m8 = 0; m8 < 4; m8++) {
            float4 p = p4[m8];
            float4 v0 = s4[m8 * 2], v1 = s4[m8 * 2 + 1];
            float pa = p.x * scale, pb = p.y * scale, pc = p.z * scale, pd = p.w * scale;
            x[m8 * 4 + 0] = make_float2(v0.x * pa, v0.y * pa);
            x[m8 * 4 + 1] = make_float2(v0.z * pb, v0.w * pb);
            x[m8 * 4 + 2] = make_float2(v1.x * pc, v1.y * pc);
            x[m8 * 4 + 3] = make_float2(v1.z * pd, v1.w * pd);
        }
        comb_regs<true>(x, s_twr, s_twi);
        int rbase = r * 129 + ((r >> 4) << 1) + (n << 4);
        float2 w = make_float2(1.f, 0.f);
#pragma unroll
        for (int j = 0; j < 16; j++) {
            float2 z = cmul(x[j], w);
            z = lane_dft8_inv(z, k);
            sc[rbase + ((j + 2 * n) & 15)] = z;   // c = 16n + j, swizzled
            w = cmul(w, c128);
        }
    }
    __syncthreads();

    // ---- dim1 (along r): strided swizzled loads, inverse in regs, |.| ------
    float local = 0.f;
#pragma unroll
    for (int it = 0; it < 2; it++) {
        int c = grp + (it << 6);
        int o = smaddr(0, c);         // column offset (swizzle of c only)
        float2 x[16];
#pragma unroll
        for (int j = 0; j < 16; j++) {
            int p = 16 * k + j;
            x[j] = sc[p * 129 + (k << 1) + o];
        }
        comb_regs<true>(x, s_twr, s_twi);
        float2 w = make_float2(1.f, 0.f);
#pragma unroll
        for (int j = 0; j < 16; j++) {
            float2 z = cmul(x[j], w);
            z = lane_dft8_inv(z, k);
            local += sqrtf(z.x * z.x + z.y * z.y);
            w = cmul(w, c128);
        }
    }
    float s = block_sum(local, red);
    if (tid == 0) g_s2part[bi] = s;
}

// ---------------- stage D: deterministic reduce + MLP ------------------------
__global__ void kD(const float* __restrict__ fc1w, const float* __restrict__ fc1b,
                   const float* __restrict__ fc2w, const float* __restrict__ fc2b,
                   float* __restrict__ out) {
    int b = threadIdx.x;
    if (b >= 64) return;
    float s[11];
    s[0] = g_s0[b];
    for (int j = 0; j < 4; j++) {
        float acc = 0.f;
        for (int l = 0; l < 4; l++) acc += g_s1part[b * 16 + j * 4 + l];
        s[1 + j] = acc * (1.f / (4.f * 16384.f));
    }
    for (int p = 0; p < 6; p++) {
        float acc = 0.f;
        for (int kk = 0; kk < 16; kk++) acc += g_s2part[b * 96 + p * 16 + kk];
        s[5 + p] = acc * (1.f / (16.f * 16384.f));
    }
    float h[4];
    for (int i = 0; i < 4; i++) {
        float a = fc1b[i];
        for (int t = 0; t < 11; t++) a += fc1w[i * 11 + t] * s[t];
        h[i] = fmaxf(a, 0.f);
    }
    for (int kk = 0; kk < 10; kk++) {
        float a = fc2b[kk];
        for (int i = 0; i < 4; i++) a += fc2w[kk * 4 + i] * h[i];
        out[b * 10 + kk] = 1.f / (1.f + expf(-a));
    }
}

// ---------------- launch -----------------------------------------------------
extern "C" void kernel_launch(void* const* d_in, const int* in_sizes, int n_in,
                              void* d_out, int out_size) {
    const float* img  = (const float*)d_in[0];
    const float* fc1w = (const float*)d_in[1];
    const float* fc1b = (const float*)d_in[2];
    const float* fc2w = (const float*)d_in[3];
    const float* fc2b = (const float*)d_in[4];
    float* out = (float*)d_out;

    const size_t smem = 16544 * sizeof(float2);   // 132352 B (covers both layouts)
    cudaFuncSetAttribute(kA, cudaFuncAttributeMaxDynamicSharedMemorySize, (int)smem);
    cudaFuncSetAttribute(kB, cudaFuncAttributeMaxDynamicSharedMemorySize, (int)smem);
    cudaFuncSetAttribute(kC, cudaFuncAttributeMaxDynamicSharedMemorySize, (int)smem);

    init_psi_kernel<<<256, 1024>>>();
    kA<<<64, NT, smem>>>(img);
    kB<<<1024, NT, smem>>>();
    kC<<<6144, NT, smem>>>();
    kD<<<1, 64>>>(fc1w, fc1b, fc2w, fc2b, out);
}

// round 9
// speedup vs baseline: 1.3686x; 1.3686x over previous
#include <cuda_runtime.h>
#include <math.h>

#define NPAD 129
#define NT   512
#define PI_F 3.14159265358979f

// kC layout: row stride 130 float2 = 65 float4 (odd -> conflict-free)
#define NP4  65

// ---------------- device scratch (static: no allocation allowed) -------------
__device__ float2 g_ihat [64  * 16384];    // FFT2(image), digit-rev layout
__device__ float2 g_u1hat[1024 * 16384];   // FFT2(|u1|),  digit-rev layout
__device__ float  g_psi  [16  * 16384];    // Morlet bank, digit-rev layout
__device__ float  g_s0   [64];
__device__ float  g_s1part[1024];
__device__ float  g_s2part[6144];

// digit-reversal for radix [8,4,4] DIF: freq f -> storage position
__device__ __forceinline__ int dperm(int f) {
    return ((f & 7) << 4) | (((f >> 3) & 3) << 2) | (f >> 5);
}

// ---------------- filter bank, stored pre-permuted ---------------------------
__global__ void init_psi_kernel() {
    int idx = blockIdx.x * blockDim.x + threadIdx.x;
    if (idx >= 16 * 16384) return;
    int fc = idx & 127;
    int fr = (idx >> 7) & 127;
    int l  = (idx >> 14) & 3;
    int j  = idx >> 16;
    const float w = 2.f * PI_F / 128.f;
    float fx = (float)((fr < 64) ? fr : fr - 128) * w;
    float fy = (float)((fc < 64) ? fc : fc - 128) * w;
    float k0 = (3.f * PI_F / 4.f) / (float)(1 << j);
    float sg = 0.8f * (float)(1 << j);
    float th = PI_F * (float)l / 4.f;
    float k0x = k0 * cosf(th), k0y = k0 * sinf(th);
    float hs = 0.5f * sg * sg;
    float beta = expf(-hs * k0 * k0);
    float gs = expf(-hs * ((fx - k0x) * (fx - k0x) + (fy - k0y) * (fy - k0y)));
    float g0 = expf(-hs * (fx * fx + fy * fy));
    g_psi[((j * 4 + l) << 14) + (dperm(fr) << 7) + dperm(fc)] = gs - beta * g0;
}

// ---------------- register butterflies (interleaved complex) -----------------
template <bool INV>
__device__ __forceinline__ void bfly4(float2* x) {
    float t0r = x[0].x + x[2].x, t0i = x[0].y + x[2].y;
    float t1r = x[0].x - x[2].x, t1i = x[0].y - x[2].y;
    float t2r = x[1].x + x[3].x, t2i = x[1].y + x[3].y;
    float t3r = x[1].x - x[3].x, t3i = x[1].y - x[3].y;
    x[0].x = t0r + t2r; x[0].y = t0i + t2i;
    x[2].x = t0r - t2r; x[2].y = t0i - t2i;
    if (!INV) {
        x[1].x = t1r + t3i; x[1].y = t1i - t3r;
        x[3].x = t1r - t3i; x[3].y = t1i + t3r;
    } else {
        x[1].x = t1r - t3i; x[1].y = t1i + t3r;
        x[3].x = t1r + t3i; x[3].y = t1i - t3r;
    }
}

template <bool INV>
__device__ __forceinline__ void bfly8(float2* x) {
    const float C = 0.70710678118654752f;
    float t0r = x[0].x + x[4].x, t0i = x[0].y + x[4].y;
    float t1r = x[0].x - x[4].x, t1i = x[0].y - x[4].y;
    float t2r = x[2].x + x[6].x, t2i = x[2].y + x[6].y;
    float t3r = x[2].x - x[6].x, t3i = x[2].y - x[6].y;
    float e0r = t0r + t2r, e0i = t0i + t2i;
    float e2r = t0r - t2r, e2i = t0i - t2i;
    float e1r, e1i, e3r, e3i;
    if (!INV) { e1r = t1r + t3i; e1i = t1i - t3r; e3r = t1r - t3i; e3i = t1i + t3r; }
    else      { e1r = t1r - t3i; e1i = t1i + t3r; e3r = t1r + t3i; e3i = t1i - t3r; }
    float u0r = x[1].x + x[5].x, u0i = x[1].y + x[5].y;
    float u1r = x[1].x - x[5].x, u1i = x[1].y - x[5].y;
    float u2r = x[3].x + x[7].x, u2i = x[3].y + x[7].y;
    float u3r = x[3].x - x[7].x, u3i = x[3].y - x[7].y;
    float o0r = u0r + u2r, o0i = u0i + u2i;
    float o2r = u0r - u2r, o2i = u0i - u2i;
    float o1r, o1i, o3r, o3i;
    if (!INV) { o1r = u1r + u3i; o1i = u1i - u3r; o3r = u1r - u3i; o3i = u1i + u3r; }
    else      { o1r = u1r - u3i; o1i = u1i + u3r; o3r = u1r + u3i; o3i = u1i - u3r; }
    float w1r, w1i, w2r, w2i, w3r, w3i;
    if (!INV) {
        w1r = C * (o1r + o1i); w1i = C * (o1i - o1r);
        w2r = o2i;             w2i = -o2r;
        w3r = C * (o3i - o3r); w3i = -C * (o3r + o3i);
    } else {
        w1r = C * (o1r - o1i); w1i = C * (o1i + o1r);
        w2r = -o2i;            w2i = o2r;
        w3r = -C * (o3r + o3i); w3i = C * (o3r - o3i);
    }
    x[0].x = e0r + o0r; x[0].y = e0i + o0i;
    x[1].x = e1r + w1r; x[1].y = e1i + w1i;
    x[2].x = e2r + w2r; x[2].y = e2i + w2i;
    x[3].x = e3r + w3r; x[3].y = e3i + w3i;
    x[4].x = e0r - o0r; x[4].y = e0i - o0i;
    x[5].x = e1r - w1r; x[5].y = e1i - w1i;
    x[6].x = e2r - w2r; x[6].y = e2i - w2i;
    x[7].x = e3r - w3r; x[7].y = e3i - w3i;
}

// ---- combined [r4-mid (stride4) + r4-last (stride1)] on 16 register points --
template <bool INV>
__device__ __forceinline__ void comb_regs(float2* x, const float* twr, const float* twi) {
    if (!INV) {
#pragma unroll
        for (int j = 0; j < 4; j++) {
            float2 y[4];
#pragma unroll
            for (int k = 0; k < 4; k++) y[k] = x[j + 4 * k];
            bfly4<false>(y);
#pragma unroll
            for (int k = 1; k < 4; k++) {
                int ti = 8 * j * k;
                float wr = twr[ti], wi = twi[ti];
                float a = y[k].x, b = y[k].y;
                y[k].x = a * wr - b * wi; y[k].y = a * wi + b * wr;
            }
#pragma unroll
            for (int k = 0; k < 4; k++) x[j + 4 * k] = y[k];
        }
#pragma unroll
        for (int a = 0; a < 4; a++) bfly4<false>(&x[4 * a]);
    } else {
#pragma unroll
        for (int a = 0; a < 4; a++) bfly4<true>(&x[4 * a]);
#pragma unroll
        for (int j = 0; j < 4; j++) {
            float2 y[4];
#pragma unroll
            for (int k = 0; k < 4; k++) y[k] = x[j + 4 * k];
#pragma unroll
            for (int k = 1; k < 4; k++) {
                int ti = 8 * j * k;
                float wr = twr[ti], wi = -twi[ti];
                float a = y[k].x, b = y[k].y;
                y[k].x = a * wr - b * wi; y[k].y = a * wi + b * wr;
            }
            bfly4<true>(y);
#pragma unroll
            for (int k = 0; k < 4; k++) x[j + 4 * k] = y[k];
        }
    }
}

// ---------------- smem passes (NPAD=129 layout, used by kA / kB) -------------
template <bool INV, int DIM>
__device__ __forceinline__ void comb_stage(float2* sc, const float* twr, const float* twi) {
    for (int idx = threadIdx.x; idx < 1024; idx += NT) {
        int q = idx & 127, g = idx >> 7;
        int base = (DIM == 0) ? q * NPAD + (g << 4) : (g << 4) * NPAD + q;
        int step = (DIM == 0) ? 1 : NPAD;
        float2 x[16];
#pragma unroll
        for (int m = 0; m < 16; m++) x[m] = sc[base + m * step];
        comb_regs<INV>(x, twr, twi);
#pragma unroll
        for (int m = 0; m < 16; m++) sc[base + m * step] = x[m];
    }
    __syncthreads();
}

template <bool INV, int DIM>
__device__ __forceinline__ void r8_stage(float2* sc, const float* twr, const float* twi) {
    for (int idx = threadIdx.x; idx < 2048; idx += NT) {
        int q = idx & 127, j = idx >> 7;
        int base = (DIM == 0) ? q * NPAD + j : j * NPAD + q;
        int step = (DIM == 0) ? 16 : 16 * NPAD;
        float2 x[8];
#pragma unroll
        for (int k = 0; k < 8; k++) x[k] = sc[base + k * step];
        if (INV) {
#pragma unroll
            for (int k = 1; k < 8; k++) {
                int t = j * k;
                float wr = twr[t], wi = -twi[t];
                float a = x[k].x, b = x[k].y;
                x[k].x = a * wr - b * wi; x[k].y = a * wi + b * wr;
            }
        }
        bfly8<INV>(x);
        if (!INV) {
#pragma unroll
            for (int k = 1; k < 8; k++) {
                int t = j * k;
                float wr = twr[t], wi = twi[t];
                float a = x[k].x, b = x[k].y;
                x[k].x = a * wr - b * wi; x[k].y = a * wi + b * wr;
            }
        }
#pragma unroll
        for (int k = 0; k < 8; k++) sc[base + k * step] = x[k];
    }
    __syncthreads();
}

__device__ __forceinline__ void pass_load_inv0(float2* sc, const float2* __restrict__ src,
                                               const float* __restrict__ psi,
                                               const float* twr, const float* twi) {
    const float scale = 1.f / 16384.f;
    for (int idx = threadIdx.x; idx < 1024; idx += NT) {
        int rr = idx & 127, g = idx >> 7;
        int gbase = rr * 128 + (g << 4);
        const float4* s4 = reinterpret_cast<const float4*>(src + gbase);
        const float4* p4 = reinterpret_cast<const float4*>(psi + gbase);
        float2 x[16];
#pragma unroll
        for (int m8 = 0; m8 < 4; m8++) {
            float4 p = p4[m8];
            float4 v0 = s4[m8 * 2], v1 = s4[m8 * 2 + 1];
            float pa = p.x * scale, pb = p.y * scale, pc = p.z * scale, pd = p.w * scale;
            x[m8 * 4 + 0] = make_float2(v0.x * pa, v0.y * pa);
            x[m8 * 4 + 1] = make_float2(v0.z * pb, v0.w * pb);
            x[m8 * 4 + 2] = make_float2(v1.x * pc, v1.y * pc);
            x[m8 * 4 + 3] = make_float2(v1.z * pd, v1.w * pd);
        }
        comb_regs<true>(x, twr, twi);
        int base = rr * NPAD + (g << 4);
#pragma unroll
        for (int m = 0; m < 16; m++) sc[base + m] = x[m];
    }
    __syncthreads();
}

template <bool WRITE>
__device__ __forceinline__ float pass_inv1_r8_mag(float2* sc, const float* twr, const float* twi) {
    float local = 0.f;
    for (int idx = threadIdx.x; idx < 2048; idx += NT) {
        int q = idx & 127, j = idx >> 7;
        int base = j * NPAD + q;
        int step = 16 * NPAD;
        float2 x[8];
#pragma unroll
        for (int k = 0; k < 8; k++) x[k] = sc[base + k * step];
#pragma unroll
        for (int k = 1; k < 8; k++) {
            int t = j * k;
            float wr = twr[t], wi = -twi[t];
            float a = x[k].x, b = x[k].y;
            x[k].x = a * wr - b * wi; x[k].y = a * wi + b * wr;
        }
        bfly8<true>(x);
#pragma unroll
        for (int k = 0; k < 8; k++) {
            float mag = sqrtf(x[k].x * x[k].x + x[k].y * x[k].y);
            local += mag;
            if (WRITE) sc[base + k * step] = make_float2(mag, 0.f);
        }
    }
    __syncthreads();
    return local;
}

__device__ __forceinline__ void pass_fwd1_store(float2* sc, float2* __restrict__ dst,
                                                const float* twr, const float* twi) {
    for (int idx = threadIdx.x; idx < 1024; idx += NT) {
        int q = idx & 127, g = idx >> 7;
        int base = (g << 4) * NPAD + q;
        float2 x[16];
#pragma unroll
        for (int m = 0; m < 16; m++) x[m] = sc[base + m * NPAD];
        comb_regs<false>(x, twr, twi);
#pragma unroll
        for (int m = 0; m < 16; m++) dst[((g << 4) + m) * 128 + q] = x[m];
    }
}

#define INIT_TWIDDLES()                                                        \
    do {                                                                       \
        if (threadIdx.x < 128) {                                               \
            float sv, cv;                                                      \
            __sincosf(-2.f * PI_F * (float)threadIdx.x / 128.f, &sv, &cv);     \
            s_twr[threadIdx.x] = cv;                                           \
            s_twi[threadIdx.x] = sv;                                           \
        }                                                                      \
    } while (0)

// warp-shuffle block reduction (deterministic); result valid in tid 0
__device__ __forceinline__ float block_sum(float v, float* red) {
#pragma unroll
    for (int o = 16; o; o >>= 1) v += __shfl_xor_sync(0xffffffffu, v, o);
    if ((threadIdx.x & 31) == 0) red[threadIdx.x >> 5] = v;
    __syncthreads();
    float s = 0.f;
    if (threadIdx.x < 32) {
        s = (threadIdx.x < NT / 32) ? red[threadIdx.x] : 0.f;
#pragma unroll
        for (int o = 16; o; o >>= 1) s += __shfl_xor_sync(0xffffffffu, s, o);
    }
    return s;
}

// ---------------- stage A: i_hat = FFT2(image), s0 ---------------------------
__global__ __launch_bounds__(NT, 1) void kA(const float* __restrict__ img) {
    extern __shared__ float2 sc[];
    __shared__ float s_twr[128], s_twi[128];
    __shared__ float red[NT / 32];
    int b = blockIdx.x;
    int tid = threadIdx.x;
    INIT_TWIDDLES();

    float local = 0.f;
    for (int idx = tid; idx < 16384; idx += NT) {
        float v = img[b * 16384 + idx];
        int r = idx >> 7, c = idx & 127;
        sc[r * NPAD + c] = make_float2(v, 0.f);
        local += v;
    }
    float s = block_sum(local, red);
    if (tid == 0) g_s0[b] = s * (1.f / 16384.f);
    __syncthreads();

    r8_stage<false, 0>(sc, s_twr, s_twi);
    comb_stage<false, 0>(sc, s_twr, s_twi);
    r8_stage<false, 1>(sc, s_twr, s_twi);
    comb_stage<false, 1>(sc, s_twr, s_twi);

    for (int idx = tid; idx < 16384; idx += NT) {
        int r = idx >> 7, c = idx & 127;
        g_ihat[b * 16384 + idx] = sc[r * NPAD + c];
    }
}

// ---------------- stage B: u1 = |ifft2(i_hat*psi)|, s1 partial, u1_hat -------
__global__ __launch_bounds__(NT, 1) void kB() {
    extern __shared__ float2 sc[];
    __shared__ float s_twr[128], s_twi[128];
    __shared__ float red[NT / 32];
    int bi = blockIdx.x;              // b*16 + j1*4 + l1
    int b  = bi >> 4;
    int j1 = (bi >> 2) & 3;
    int tid = threadIdx.x;
    INIT_TWIDDLES();
    __syncthreads();

    const float2* src = g_ihat + (size_t)b * 16384;
    const float*  psi1 = g_psi + (((size_t)(bi & 15)) << 14);

    pass_load_inv0(sc, src, psi1, s_twr, s_twi);
    r8_stage<true, 0>(sc, s_twr, s_twi);
    comb_stage<true, 1>(sc, s_twr, s_twi);
    float local = pass_inv1_r8_mag<true>(sc, s_twr, s_twi);
    float s = block_sum(local, red);
    if (tid == 0) g_s1part[bi] = s;
    __syncthreads();

    if (j1 < 3) {                     // j1 == 3 never consumed by second order
        r8_stage<false, 0>(sc, s_twr, s_twi);
        comb_stage<false, 0>(sc, s_twr, s_twi);
        r8_stage<false, 1>(sc, s_twr, s_twi);
        pass_fwd1_store(sc, g_u1hat + (size_t)bi * 16384, s_twr, s_twi);
    }
}

// ---------------- stage C: float4-paired passes, stride-65-float4 layout -----
__global__ __launch_bounds__(NT, 1) void kC() {
    extern __shared__ float4 sf4[];   // 128 rows x 65 float4
    __shared__ float s_twr[128], s_twi[128];
    __shared__ float red[NT / 32];
    int bi = blockIdx.x;              // b*96 + pair*16 + l1*4 + l2
    int b    = bi / 96;
    int r96  = bi % 96;
    int pair = r96 >> 4;
    int l1   = (r96 >> 2) & 3;
    int l2   = r96 & 3;
    const int J1[6] = {0, 0, 0, 1, 1, 2};
    const int J2[6] = {1, 2, 3, 2, 3, 3};
    int j1 = J1[pair], j2 = J2[pair];
    int tid = threadIdx.x;
    INIT_TWIDDLES();
    __syncthreads();

    const float2* src = g_u1hat + (((size_t)b * 16 + j1 * 4 + l1) << 14);
    const float*  psi = g_psi + (((size_t)j2 * 4 + l2) << 14);
    const float scale = 1.f / 16384.f;

    // ---- C1: gmem load * psi -> comb_inv (dim0) -> smem (8x STS.128) -------
#pragma unroll
    for (int it = 0; it < 2; it++) {
        int idx = tid + it * NT;
        int r = idx & 127, g = idx >> 7;
        int gbase = r * 128 + (g << 4);
        const float4* s4 = reinterpret_cast<const float4*>(src + gbase);
        const float4* p4 = reinterpret_cast<const float4*>(psi + gbase);
        float2 x[16];
#pragma unroll
        for (int m8 = 0; m8 < 4; m8++) {
            float4 p = p4[m8];
            float4 v0 = s4[m8 * 2], v1 = s4[m8 * 2 + 1];
            float pa = p.x * scale, pb = p.y * scale, pc = p.z * scale, pd = p.w * scale;
            x[m8 * 4 + 0] = make_float2(v0.x * pa, v0.y * pa);
            x[m8 * 4 + 1] = make_float2(v0.z * pb, v0.w * pb);
            x[m8 * 4 + 2] = make_float2(v1.x * pc, v1.y * pc);
            x[m8 * 4 + 3] = make_float2(v1.z * pd, v1.w * pd);
        }
        comb_regs<true>(x, s_twr, s_twi);
        int base = r * NP4 + (g << 3);
#pragma unroll
        for (int m = 0; m < 8; m++)
            sf4[base + m] = make_float4(x[2 * m].x, x[2 * m].y, x[2 * m + 1].x, x[2 * m + 1].y);
    }
    __syncthreads();

    // ---- C2: inverse r8 along dim0 (c), two butterflies (j, j+1) per thread -
#pragma unroll
    for (int it = 0; it < 2; it++) {
        int idx = tid + it * NT;
        int q = idx & 127, jp = idx >> 7;          // jp in [0,8)
        int base = q * NP4 + jp;
        float2 xa[8], xb[8];
#pragma unroll
        for (int k = 0; k < 8; k++) {
            float4 y = sf4[base + 8 * k];
            xa[k] = make_float2(y.x, y.y);
            xb[k] = make_float2(y.z, y.w);
        }
        int j0 = 2 * jp, j1b = 2 * jp + 1;
#pragma unroll
        for (int k = 1; k < 8; k++) {
            float wr = s_twr[j0 * k], wi = -s_twi[j0 * k];
            float a = xa[k].x, bb = xa[k].y;
            xa[k].x = a * wr - bb * wi; xa[k].y = a * wi + bb * wr;
            wr = s_twr[j1b * k]; wi = -s_twi[j1b * k];
            a = xb[k].x; bb = xb[k].y;
            xb[k].x = a * wr - bb * wi; xb[k].y = a * wi + bb * wr;
        }
        bfly8<true>(xa);
        bfly8<true>(xb);
#pragma unroll
        for (int k = 0; k < 8; k++)
            sf4[base + 8 * k] = make_float4(xa[k].x, xa[k].y, xb[k].x, xb[k].y);
    }
    __syncthreads();

    // ---- C3: inverse comb along dim1 (r), two columns per thread ------------
    {
        int q = tid & 63, g = tid >> 6;            // g in [0,8)
        int base = (g << 4) * NP4 + q;
        float2 xa[16], xb[16];
#pragma unroll
        for (int m = 0; m < 16; m++) {
            float4 y = sf4[base + m * NP4];
            xa[m] = make_float2(y.x, y.y);
            xb[m] = make_float2(y.z, y.w);
        }
        comb_regs<true>(xa, s_twr, s_twi);
        comb_regs<true>(xb, s_twr, s_twi);
#pragma unroll
        for (int m = 0; m < 16; m++)
            sf4[base + m * NP4] = make_float4(xa[m].x, xa[m].y, xb[m].x, xb[m].y);
    }
    __syncthreads();

    // ---- C4: inverse r8 along dim1 + |.| (read-only) ------------------------
    float local = 0.f;
#pragma unroll
    for (int it = 0; it < 2; it++) {
        int idx = tid + it * NT;
        int q = idx & 63, j = idx >> 6;            // j in [0,16)
        int base = j * NP4 + q;
        float2 xa[8], xb[8];
#pragma unroll
        for (int k = 0; k < 8; k++) {
            float4 y = sf4[base + 16 * k * NP4];
            xa[k] = make_float2(y.x, y.y);
            xb[k] = make_float2(y.z, y.w);
        }
#pragma unroll
        for (int k = 1; k < 8; k++) {
            float wr = s_twr[j * k], wi = -s_twi[j * k];
            float a = xa[k].x, bb = xa[k].y;
            xa[k].x = a * wr - bb * wi; xa[k].y = a * wi + bb * wr;
            a = xb[k].x; bb = xb[k].y;
            xb[k].x = a * wr - bb * wi; xb[k].y = a * wi + bb * wr;
        }
        bfly8<true>(xa);
        bfly8<true>(xb);
#pragma unroll
        for (int k = 0; k < 8; k++) {
            local += sqrtf(xa[k].x * xa[k].x + xa[k].y * xa[k].y);
            local += sqrtf(xb[k].x * xb[k].x + xb[k].y * xb[k].y);
        }
    }
    float s = block_sum(local, red);
    if (tid == 0) g_s2part[bi] = s;
}

// ---------------- stage D: deterministic reduce + MLP ------------------------
__global__ void kD(const float* __restrict__ fc1w, const float* __restrict__ fc1b,
                   const float* __restrict__ fc2w, const float* __restrict__ fc2b,
                   float* __restrict__ out) {
    int b = threadIdx.x;
    if (b >= 64) return;
    float s[11];
    s[0] = g_s0[b];
    for (int j = 0; j < 4; j++) {
        float acc = 0.f;
        for (int l = 0; l < 4; l++) acc += g_s1part[b * 16 + j * 4 + l];
        s[1 + j] = acc * (1.f / (4.f * 16384.f));
    }
    for (int p = 0; p < 6; p++) {
        float acc = 0.f;
        for (int kk = 0; kk < 16; kk++) acc += g_s2part[b * 96 + p * 16 + kk];
        s[5 + p] = acc * (1.f / (16.f * 16384.f));
    }
    float h[4];
    for (int i = 0; i < 4; i++) {
        float a = fc1b[i];
        for (int t = 0; t < 11; t++) a += fc1w[i * 11 + t] * s[t];
        h[i] = fmaxf(a, 0.f);
    }
    for (int kk = 0; kk < 10; kk++) {
        float a = fc2b[kk];
        for (int i = 0; i < 4; i++) a += fc2w[kk * 4 + i] * h[i];
        out[b * 10 + kk] = 1.f / (1.f + expf(-a));
    }
}

// ---------------- launch -----------------------------------------------------
extern "C" void kernel_launch(void* const* d_in, const int* in_sizes, int n_in,
                              void* d_out, int out_size) {
    const float* img  = (const float*)d_in[0];
    const float* fc1w = (const float*)d_in[1];
    const float* fc1b = (const float*)d_in[2];
    const float* fc2w = (const float*)d_in[3];
    const float* fc2b = (const float*)d_in[4];
    float* out = (float*)d_out;

    const size_t smemAB = 128 * NPAD * sizeof(float2);   // 132096 B
    const size_t smemC  = 128 * NP4 * sizeof(float4);    // 133120 B
    cudaFuncSetAttribute(kA, cudaFuncAttributeMaxDynamicSharedMemorySize, (int)smemAB);
    cudaFuncSetAttribute(kB, cudaFuncAttributeMaxDynamicSharedMemorySize, (int)smemAB);
    cudaFuncSetAttribute(kC, cudaFuncAttributeMaxDynamicSharedMemorySize, (int)smemC);

    init_psi_kernel<<<256, 1024>>>();
    kA<<<64, NT, smemAB>>>(img);
    kB<<<1024, NT, smemAB>>>();
    kC<<<6144, NT, smemC>>>();
    kD<<<1, 64>>>(fc1w, fc1b, fc2w, fc2b, out);
}